// round 2
// baseline (speedup 1.0000x reference)
#include <cuda_runtime.h>

#define N_NODES 50000
#define F1 64
#define F2 128
#define F3 64
#define MAX_E 800000

// ---------------- device scratch ----------------
__device__ int   g_cnt [N_NODES];        // in-degree histogram (excl. self-loop)
__device__ int   g_off [N_NODES + 1];    // CSR row offsets
__device__ int   g_cur [N_NODES];        // scatter cursors
__device__ float g_dinv [N_NODES];
__device__ float g_dinv2[N_NODES];
struct EdgeRec { int s; float nm; };
__device__ EdgeRec g_edge[MAX_E];        // dst-grouped {src, norm}
__device__ float g_agg1[N_NODES * F1];   // Â z  (incl. self term)
__device__ float g_x   [N_NODES * F2];   // relu(Âz @ W1 + b1)
__device__ float g_h2  [N_NODES * F3];   // x @ W2
__device__ int   g_is64;

__device__ __forceinline__ int eidx(const void* ei, int is64, long long p) {
    return is64 ? (int)((const long long*)ei)[p] : ((const int*)ei)[p];
}

// ---------------- init: zero histogram + dtype detect ----------------
__global__ void init_kernel(const long long* ei, int M) {
    int i = blockIdx.x * 256 + threadIdx.x;
    if (i < M) g_cnt[i] = 0;
    if (blockIdx.x == 0 && threadIdx.x == 0) {
        bool ok = true;
#pragma unroll
        for (int k = 0; k < 8; k++) {
            long long v = ei[k];
            if (v < 0 || v >= N_NODES) ok = false;
        }
        g_is64 = ok ? 1 : 0;   // int32 read as int64 lands far out of range
    }
}

// ---------------- degree histogram ----------------
__global__ void hist_kernel(const void* ei, int nE) {
    int e = blockIdx.x * 256 + threadIdx.x;
    if (e >= nE) return;
    int d = eidx(ei, g_is64, (long long)nE + e);
    atomicAdd(&g_cnt[d], 1);
}

// ---------------- single-block scan: offsets, cursors, dinv ----------------
__global__ __launch_bounds__(1024) void scan_kernel(int M) {
    __shared__ int sums[1024];
    const int C = 49;                    // 1024*49 = 50176 >= 50000
    int t = threadIdx.x;
    int base = t * C;
    int local = 0;
    for (int i = 0; i < C; i++) {
        int idx = base + i;
        if (idx < M) local += g_cnt[idx];
    }
    sums[t] = local;
    __syncthreads();
    for (int d = 1; d < 1024; d <<= 1) {
        int v = (t >= d) ? sums[t - d] : 0;
        __syncthreads();
        sums[t] += v;
        __syncthreads();
    }
    int run = sums[t] - local;           // exclusive prefix for this chunk
    for (int i = 0; i < C; i++) {
        int idx = base + i;
        if (idx < M) {
            int c = g_cnt[idx];
            g_off[idx] = run;
            g_cur[idx] = run;
            float r = rsqrtf((float)(c + 1));   // +1 self-loop
            g_dinv[idx]  = r;
            g_dinv2[idx] = r * r;
            run += c;
        }
    }
    if (t == 1023) g_off[M] = run;       // == nE
}

// ---------------- scatter edges into CSR with fused norm ----------------
__global__ void scatter_kernel(const void* ei, int nE) {
    int e = blockIdx.x * 256 + threadIdx.x;
    if (e >= nE) return;
    int is64 = g_is64;
    int s = eidx(ei, is64, e);
    int d = eidx(ei, is64, (long long)nE + e);
    int pos = atomicAdd(&g_cur[d], 1);
    EdgeRec ed;
    ed.s  = s;
    ed.nm = g_dinv[s] * g_dinv[d];
    g_edge[pos] = ed;
}

// ---------------- CSR aggregation, warp per node (64-wide features) ----------------
// lanes 0-15 / 16-31 handle even/odd edges; shfl_xor(16) combines.
__global__ __launch_bounds__(256) void agg1_csr(const float4* __restrict__ z4, int M) {
    int w = (blockIdx.x * 256 + threadIdx.x) >> 5;
    if (w >= M) return;
    int lane = threadIdx.x & 31;
    int half = lane >> 4, j = lane & 15;
    int k1 = g_off[w + 1];
    float4 acc = make_float4(0.f, 0.f, 0.f, 0.f);
    for (int k = g_off[w] + half; k < k1; k += 2) {
        EdgeRec ed = g_edge[k];
        float4 v = z4[(long long)ed.s * 16 + j];
        acc.x += v.x * ed.nm; acc.y += v.y * ed.nm;
        acc.z += v.z * ed.nm; acc.w += v.w * ed.nm;
    }
    acc.x += __shfl_xor_sync(0xffffffffu, acc.x, 16);
    acc.y += __shfl_xor_sync(0xffffffffu, acc.y, 16);
    acc.z += __shfl_xor_sync(0xffffffffu, acc.z, 16);
    acc.w += __shfl_xor_sync(0xffffffffu, acc.w, 16);
    if (half == 0) {
        float s2 = g_dinv2[w];
        float4 v = z4[(long long)w * 16 + j];      // self-loop term
        acc.x += v.x * s2; acc.y += v.y * s2;
        acc.z += v.z * s2; acc.w += v.w * s2;
        ((float4*)g_agg1)[(long long)w * 16 + j] = acc;
    }
}

// layer-2 agg fused with bias + relu, writes straight to output
__global__ __launch_bounds__(256) void agg2_csr(const float* __restrict__ b2,
                                                float* __restrict__ out, int M) {
    int w = (blockIdx.x * 256 + threadIdx.x) >> 5;
    if (w >= M) return;
    int lane = threadIdx.x & 31;
    int half = lane >> 4, j = lane & 15;
    const float4* h4 = (const float4*)g_h2;
    int k1 = g_off[w + 1];
    float4 acc = make_float4(0.f, 0.f, 0.f, 0.f);
    for (int k = g_off[w] + half; k < k1; k += 2) {
        EdgeRec ed = g_edge[k];
        float4 v = h4[(long long)ed.s * 16 + j];
        acc.x += v.x * ed.nm; acc.y += v.y * ed.nm;
        acc.z += v.z * ed.nm; acc.w += v.w * ed.nm;
    }
    acc.x += __shfl_xor_sync(0xffffffffu, acc.x, 16);
    acc.y += __shfl_xor_sync(0xffffffffu, acc.y, 16);
    acc.z += __shfl_xor_sync(0xffffffffu, acc.z, 16);
    acc.w += __shfl_xor_sync(0xffffffffu, acc.w, 16);
    if (half == 0) {
        float s2 = g_dinv2[w];
        float4 v = h4[(long long)w * 16 + j];
        float4 b = *(const float4*)(b2 + j * 4);
        float4 o;
        o.x = fmaxf(acc.x + v.x * s2 + b.x, 0.f);
        o.y = fmaxf(acc.y + v.y * s2 + b.y, 0.f);
        o.z = fmaxf(acc.z + v.z * s2 + b.z, 0.f);
        o.w = fmaxf(acc.w + v.w * s2 + b.w, 0.f);
        ((float4*)out)[(long long)w * 16 + j] = o;
    }
}

// ---------------- GEMM1: x = relu( agg1 @ W1 + b1 )  [M,64]x[64,128] ----------------
__global__ __launch_bounds__(256) void gemm1_kernel(const float* __restrict__ W1,
                                                    const float* __restrict__ b1,
                                                    int M) {
    __shared__ float  Ws[F1 * F2];        // 32 KB
    __shared__ float4 As4[64 * 16];       // 16 KB
    int tid = threadIdx.x;
    int m0  = blockIdx.x * 64;

    const float4* W14 = (const float4*)W1;
    float4* Ws4 = (float4*)Ws;
#pragma unroll
    for (int i = 0; i < 8; i++) Ws4[tid + 256 * i] = W14[tid + 256 * i];

    const float4* ag4 = (const float4*)g_agg1;
#pragma unroll
    for (int i = 0; i < 4; i++) {
        int t   = tid + 256 * i;
        int row = m0 + (t >> 4);
        As4[t] = (row < M) ? ag4[(long long)row * 16 + (t & 15)]
                           : make_float4(0.f, 0.f, 0.f, 0.f);
    }
    __syncthreads();

    int tx = tid & 31, ty = tid >> 5;
    int c = tx * 4, r0 = ty * 8;
    float acc[8][4];
#pragma unroll
    for (int i = 0; i < 8; i++)
#pragma unroll
        for (int jj = 0; jj < 4; jj++) acc[i][jj] = 0.f;

    const float* As = (const float*)As4;
#pragma unroll
    for (int k = 0; k < F1; k++) {
        float4 wv = *(const float4*)&Ws[k * F2 + c];
#pragma unroll
        for (int i = 0; i < 8; i++) {
            float a = As[(r0 + i) * F1 + k];
            acc[i][0] += a * wv.x;
            acc[i][1] += a * wv.y;
            acc[i][2] += a * wv.z;
            acc[i][3] += a * wv.w;
        }
    }

    float4 bb = *(const float4*)&b1[c];
#pragma unroll
    for (int i = 0; i < 8; i++) {
        int m = m0 + r0 + i;
        if (m < M) {
            float4 o;
            o.x = fmaxf(acc[i][0] + bb.x, 0.f);
            o.y = fmaxf(acc[i][1] + bb.y, 0.f);
            o.z = fmaxf(acc[i][2] + bb.z, 0.f);
            o.w = fmaxf(acc[i][3] + bb.w, 0.f);
            ((float4*)g_x)[(long long)m * 32 + tx] = o;
        }
    }
}

// ---------------- GEMM2: h2 = x @ W2   [M,128]x[128,64] ----------------
__global__ __launch_bounds__(256) void gemm2_kernel(const float* __restrict__ W2, int M) {
    __shared__ float  Ws[F2 * F3];        // 32 KB
    __shared__ float4 As4[64 * 8];        // 8 KB
    int tid = threadIdx.x;
    int m0  = blockIdx.x * 64;

    const float4* W24 = (const float4*)W2;
    float4* Ws4 = (float4*)Ws;
#pragma unroll
    for (int i = 0; i < 8; i++) Ws4[tid + 256 * i] = W24[tid + 256 * i];

    int tx = tid & 15, ty = tid >> 4;
    float acc[4][4];
#pragma unroll
    for (int i = 0; i < 4; i++)
#pragma unroll
        for (int jj = 0; jj < 4; jj++) acc[i][jj] = 0.f;

    const float* As = (const float*)As4;
    const float4* x4 = (const float4*)g_x;

    for (int kc = 0; kc < 4; kc++) {
        __syncthreads();
#pragma unroll
        for (int i = 0; i < 2; i++) {
            int t   = tid + 256 * i;
            int row = m0 + (t >> 3);
            int c4  = t & 7;
            As4[t] = (row < M) ? x4[(long long)row * 32 + kc * 8 + c4]
                               : make_float4(0.f, 0.f, 0.f, 0.f);
        }
        __syncthreads();
#pragma unroll
        for (int kk = 0; kk < 32; kk++) {
            int k = kc * 32 + kk;
            float4 wv = *(const float4*)&Ws[k * F3 + tx * 4];
#pragma unroll
            for (int i = 0; i < 4; i++) {
                float a = As[(ty * 4 + i) * 32 + kk];
                acc[i][0] += a * wv.x;
                acc[i][1] += a * wv.y;
                acc[i][2] += a * wv.z;
                acc[i][3] += a * wv.w;
            }
        }
    }

#pragma unroll
    for (int i = 0; i < 4; i++) {
        int m = m0 + ty * 4 + i;
        if (m < M) {
            ((float4*)g_h2)[(long long)m * 16 + tx] =
                make_float4(acc[i][0], acc[i][1], acc[i][2], acc[i][3]);
        }
    }
}

// ---------------- launch ----------------
extern "C" void kernel_launch(void* const* d_in, const int* in_sizes, int n_in,
                              void* d_out, int out_size) {
    const float* z  = (const float*)d_in[0];
    const void*  ei = d_in[1];
    const float* W1 = (const float*)d_in[2];
    const float* b1 = (const float*)d_in[3];
    const float* W2 = (const float*)d_in[4];
    const float* b2 = (const float*)d_in[5];
    float* out = (float*)d_out;

    int nE = in_sizes[1] / 2;
    int M  = in_sizes[0] / F1;

    int nb_nodes = (M + 255) / 256;
    int nb_edge  = (nE + 255) / 256;
    int nb_agg   = (M * 32 + 255) / 256;     // warp per node
    int nb_gemm  = (M + 63) / 64;

    init_kernel<<<nb_nodes, 256>>>((const long long*)ei, M);
    hist_kernel<<<nb_edge, 256>>>(ei, nE);
    scan_kernel<<<1, 1024>>>(M);
    scatter_kernel<<<nb_edge, 256>>>(ei, nE);
    agg1_csr<<<nb_agg, 256>>>((const float4*)z, M);
    gemm1_kernel<<<nb_gemm, 256>>>(W1, b1, M);
    gemm2_kernel<<<nb_gemm, 256>>>(W2, M);
    agg2_csr<<<nb_agg, 256>>>(b2, out, M);
}

// round 3
// speedup vs baseline: 1.5120x; 1.5120x over previous
#include <cuda_runtime.h>

#define N_NODES 50000
#define F1 64
#define F2 128
#define F3 64
#define MAX_E 800000

// ---------------- device scratch ----------------
__device__ int   g_cnt [N_NODES];        // in-degree (excl. self-loop)
__device__ int2  g_ed  [MAX_E];          // packed {src, dst}
__device__ float g_zs  [N_NODES * F1];   // z * dinv
__device__ float g_agg1[N_NODES * F1];   // seeded with zs, then += zs[s]
__device__ float g_x   [N_NODES * F2];   // relu(layer1)
__device__ float g_h2  [N_NODES * F3];   // x @ W2, then *= dinv in scale2
__device__ int   g_is64;

__device__ __forceinline__ void red4(float* p, float x, float y, float z, float w) {
    asm volatile("red.global.add.v4.f32 [%0], {%1,%2,%3,%4};"
                 :: "l"(p), "f"(x), "f"(y), "f"(z), "f"(w) : "memory");
}

__device__ __forceinline__ float rinv_of(int m) {
    return rsqrtf((float)(g_cnt[m] + 1));
}

// ---------------- init: zero histogram + dtype detect ----------------
__global__ void init_kernel(const long long* ei, int M) {
    int i = blockIdx.x * 256 + threadIdx.x;
    if (i < M) g_cnt[i] = 0;
    if (blockIdx.x == 0 && threadIdx.x == 0) {
        bool ok = true;
#pragma unroll
        for (int k = 0; k < 8; k++) {
            long long v = ei[k];
            if (v < 0 || v >= N_NODES) ok = false;
        }
        g_is64 = ok ? 1 : 0;   // int32 data read as int64 lands out of range
    }
}

// ---------------- pack edges to int2 + degree histogram ----------------
__global__ void pack_deg_kernel(const void* ei, int nE) {
    int e = blockIdx.x * 256 + threadIdx.x;
    if (e >= nE) return;
    int s, d;
    if (g_is64) {
        s = (int)((const long long*)ei)[e];
        d = (int)((const long long*)ei)[(long long)nE + e];
    } else {
        s = ((const int*)ei)[e];
        d = ((const int*)ei)[nE + e];
    }
    g_ed[e] = make_int2(s, d);
    atomicAdd(&g_cnt[d], 1);
}

// ---------------- scale1: zs = z*dinv, seed agg1 = zs ----------------
__global__ __launch_bounds__(256) void scale1_kernel(const float4* __restrict__ z4, int M) {
    int i = blockIdx.x * 256 + threadIdx.x;     // over M*16 float4
    if (i >= M * 16) return;
    float r = rinv_of(i >> 4);
    float4 v = z4[i];
    v.x *= r; v.y *= r; v.z *= r; v.w *= r;
    ((float4*)g_zs)[i]   = v;
    ((float4*)g_agg1)[i] = v;                   // self-loop seed
}

// ---------------- edge aggregation: agg1[d] += zs[s]  (pure copy-add) ----------------
__global__ __launch_bounds__(256) void agg1_kernel(int nE) {
    long long t = (long long)blockIdx.x * 256 + threadIdx.x;
    long long e = t >> 4;
    if (e >= nE) return;
    int j = (int)(t & 15);
    int2 ed = g_ed[e];
    float4 v = ((const float4*)g_zs)[ed.x * 16 + j];
    red4(g_agg1 + ((long long)ed.y * 16 + j) * 4, v.x, v.y, v.z, v.w);
}

// ---------------- GEMM1: x = relu( (agg1*dinv) @ W1 + b1 )  [M,64]x[64,128] ----------------
__global__ __launch_bounds__(256) void gemm1_kernel(const float* __restrict__ W1,
                                                    const float* __restrict__ b1,
                                                    int M) {
    __shared__ float  Ws[F1 * F2];        // 32 KB
    __shared__ float4 As4[64 * 16];       // 16 KB
    int tid = threadIdx.x;
    int m0  = blockIdx.x * 64;

    const float4* W14 = (const float4*)W1;
    float4* Ws4 = (float4*)Ws;
#pragma unroll
    for (int i = 0; i < 8; i++) Ws4[tid + 256 * i] = W14[tid + 256 * i];

    const float4* ag4 = (const float4*)g_agg1;
#pragma unroll
    for (int i = 0; i < 4; i++) {
        int t   = tid + 256 * i;
        int row = m0 + (t >> 4);
        float4 a = make_float4(0.f, 0.f, 0.f, 0.f);
        if (row < M) {
            a = ag4[(long long)row * 16 + (t & 15)];
            float r = rinv_of(row);
            a.x *= r; a.y *= r; a.z *= r; a.w *= r;
        }
        As4[t] = a;
    }
    __syncthreads();

    int tx = tid & 31, ty = tid >> 5;
    int c = tx * 4, r0 = ty * 8;
    float acc[8][4];
#pragma unroll
    for (int i = 0; i < 8; i++)
#pragma unroll
        for (int jj = 0; jj < 4; jj++) acc[i][jj] = 0.f;

    const float* As = (const float*)As4;
#pragma unroll
    for (int k = 0; k < F1; k++) {
        float4 wv = *(const float4*)&Ws[k * F2 + c];
#pragma unroll
        for (int i = 0; i < 8; i++) {
            float a = As[(r0 + i) * F1 + k];
            acc[i][0] += a * wv.x;
            acc[i][1] += a * wv.y;
            acc[i][2] += a * wv.z;
            acc[i][3] += a * wv.w;
        }
    }

    float4 bb = *(const float4*)&b1[c];
#pragma unroll
    for (int i = 0; i < 8; i++) {
        int m = m0 + r0 + i;
        if (m < M) {
            float4 o;
            o.x = fmaxf(acc[i][0] + bb.x, 0.f);
            o.y = fmaxf(acc[i][1] + bb.y, 0.f);
            o.z = fmaxf(acc[i][2] + bb.z, 0.f);
            o.w = fmaxf(acc[i][3] + bb.w, 0.f);
            ((float4*)g_x)[(long long)m * 32 + tx] = o;
        }
    }
}

// ---------------- GEMM2: h2 = x @ W2   [M,128]x[128,64] ----------------
__global__ __launch_bounds__(256) void gemm2_kernel(const float* __restrict__ W2, int M) {
    __shared__ float  Ws[F2 * F3];        // 32 KB
    __shared__ float4 As4[64 * 8];        // 8 KB
    int tid = threadIdx.x;
    int m0  = blockIdx.x * 64;

    const float4* W24 = (const float4*)W2;
    float4* Ws4 = (float4*)Ws;
#pragma unroll
    for (int i = 0; i < 8; i++) Ws4[tid + 256 * i] = W24[tid + 256 * i];

    int tx = tid & 15, ty = tid >> 4;
    float acc[4][4];
#pragma unroll
    for (int i = 0; i < 4; i++)
#pragma unroll
        for (int jj = 0; jj < 4; jj++) acc[i][jj] = 0.f;

    const float* As = (const float*)As4;
    const float4* x4 = (const float4*)g_x;

    for (int kc = 0; kc < 4; kc++) {
        __syncthreads();
#pragma unroll
        for (int i = 0; i < 2; i++) {
            int t   = tid + 256 * i;
            int row = m0 + (t >> 3);
            int c4  = t & 7;
            As4[t] = (row < M) ? x4[(long long)row * 32 + kc * 8 + c4]
                               : make_float4(0.f, 0.f, 0.f, 0.f);
        }
        __syncthreads();
#pragma unroll
        for (int kk = 0; kk < 32; kk++) {
            int k = kc * 32 + kk;
            float4 wv = *(const float4*)&Ws[k * F3 + tx * 4];
#pragma unroll
            for (int i = 0; i < 4; i++) {
                float a = As[(ty * 4 + i) * 32 + kk];
                acc[i][0] += a * wv.x;
                acc[i][1] += a * wv.y;
                acc[i][2] += a * wv.z;
                acc[i][3] += a * wv.w;
            }
        }
    }

#pragma unroll
    for (int i = 0; i < 4; i++) {
        int m = m0 + ty * 4 + i;
        if (m < M) {
            ((float4*)g_h2)[(long long)m * 16 + tx] =
                make_float4(acc[i][0], acc[i][1], acc[i][2], acc[i][3]);
        }
    }
}

// ---------------- scale2: h2 *= dinv (in place), seed out = h2s ----------------
__global__ __launch_bounds__(256) void scale2_kernel(float* __restrict__ out, int M) {
    int i = blockIdx.x * 256 + threadIdx.x;     // over M*16 float4
    if (i >= M * 16) return;
    float r = rinv_of(i >> 4);
    float4 v = ((const float4*)g_h2)[i];
    v.x *= r; v.y *= r; v.z *= r; v.w *= r;
    ((float4*)g_h2)[i] = v;
    ((float4*)out)[i]  = v;                     // self-loop seed
}

// ---------------- edge aggregation 2: out[d] += h2s[s] ----------------
__global__ __launch_bounds__(256) void agg2_kernel(float* __restrict__ out, int nE) {
    long long t = (long long)blockIdx.x * 256 + threadIdx.x;
    long long e = t >> 4;
    if (e >= nE) return;
    int j = (int)(t & 15);
    int2 ed = g_ed[e];
    float4 v = ((const float4*)g_h2)[ed.x * 16 + j];
    red4(out + ((long long)ed.y * 16 + j) * 4, v.x, v.y, v.z, v.w);
}

// ---------------- epilogue: out = relu(out*dinv + b2)  in place ----------------
__global__ __launch_bounds__(256) void epilogue_kernel(const float* __restrict__ b2,
                                                       float* __restrict__ out, int M) {
    int i = blockIdx.x * 256 + threadIdx.x;
    if (i >= M * 16) return;
    float r = rinv_of(i >> 4);
    float4 a = ((const float4*)out)[i];
    float4 b = *(const float4*)(b2 + (i & 15) * 4);
    float4 o;
    o.x = fmaxf(a.x * r + b.x, 0.f);
    o.y = fmaxf(a.y * r + b.y, 0.f);
    o.z = fmaxf(a.z * r + b.z, 0.f);
    o.w = fmaxf(a.w * r + b.w, 0.f);
    ((float4*)out)[i] = o;
}

// ---------------- launch ----------------
extern "C" void kernel_launch(void* const* d_in, const int* in_sizes, int n_in,
                              void* d_out, int out_size) {
    const float* z  = (const float*)d_in[0];
    const void*  ei = d_in[1];
    const float* W1 = (const float*)d_in[2];
    const float* b1 = (const float*)d_in[3];
    const float* W2 = (const float*)d_in[4];
    const float* b2 = (const float*)d_in[5];
    float* out = (float*)d_out;

    int nE = in_sizes[1] / 2;
    int M  = in_sizes[0] / F1;

    int nb_nodes = (M + 255) / 256;
    int nb_edge  = (nE + 255) / 256;
    long long aggT = (long long)nE * 16;
    int nb_agg   = (int)((aggT + 255) / 256);
    int nb_vec   = (M * 16 + 255) / 256;
    int nb_gemm  = (M + 63) / 64;

    init_kernel<<<nb_nodes, 256>>>((const long long*)ei, M);
    pack_deg_kernel<<<nb_edge, 256>>>(ei, nE);
    scale1_kernel<<<nb_vec, 256>>>((const float4*)z, M);
    agg1_kernel<<<nb_agg, 256>>>(nE);
    gemm1_kernel<<<nb_gemm, 256>>>(W1, b1, M);
    gemm2_kernel<<<nb_gemm, 256>>>(W2, M);
    scale2_kernel<<<nb_vec, 256>>>(out, M);
    agg2_kernel<<<nb_agg, 256>>>(out, nE);
    epilogue_kernel<<<nb_vec, 256>>>(b2, out, M);
}